// round 8
// baseline (speedup 1.0000x reference)
#include <cuda_runtime.h>
#include <cuda_fp16.h>
#include <cuda_bf16.h>

// ---------------------------------------------------------------------------
// GAT (2-layer, H=4, D=32, IN=128) on GB300, round 8.
// Base = R4 (best, 197us): f32x2 GEMM + fused epilogue, single-pass agg.
// Deltas: (1) duplicated-W smem -> splat-free FFMA2 mainloop (24 vs 29
// issues/k-iter); (2) agg inner gather unrolled x4; (3) layer-1 GEMM moved
// to launch slot 4 so ncu profiles it next round.
// ---------------------------------------------------------------------------

#define NN 50000
#define EE 800000
#define FDIM 128
#define NEG_SLOPE 0.2f
#define GTM 64
#define GTK 32

typedef unsigned long long ull;

// -------------------- scratch (static device globals) ----------------------
__device__ __half g_feat_h[NN * FDIM];   // 12.8 MB fp16 features, head-interleaved
__device__ float  g_h1[NN * FDIM];       // 25.6 MB layer-1 output
__device__ int    g_csr_src[EE];         //  3.2 MB
__device__ int    g_cnt[NN];
__device__ int    g_row[NN];
__device__ int    g_pos[NN];
__device__ float  g_el[NN * 4];
__device__ float  g_er[NN * 4];
__device__ int    g_bsum[64];

// -------------------- f32x2 helpers -----------------------------------------
__device__ __forceinline__ void ffma2(ull& d, ull a, ull b) {
    asm("fma.rn.f32x2 %0, %1, %2, %0;" : "+l"(d) : "l"(a), "l"(b));
}
__device__ __forceinline__ float2 unpk(ull v) {
    float2 f; asm("mov.b64 {%0, %1}, %2;" : "=f"(f.x), "=f"(f.y) : "l"(v)); return f;
}

// -------------------- math helpers ------------------------------------------
__device__ __forceinline__ float lrelu(float x) { return x > 0.f ? x : NEG_SLOPE * x; }
__device__ __forceinline__ float elu1(float x)  { return x > 0.f ? x : (__expf(x) - 1.f); }

// -------------------- CSR build --------------------------------------------
__global__ void k_zero_cnt() {
    int i = blockIdx.x * blockDim.x + threadIdx.x;
    if (i < NN) g_cnt[i] = 0;
}

__global__ void k_count(const int* __restrict__ dst) {
    int e = blockIdx.x * blockDim.x + threadIdx.x;
    if (e < EE) atomicAdd(&g_cnt[dst[e]], 1);
}

__global__ void k_scan1() {
    __shared__ int sm[1024];
    int i = blockIdx.x * 1024 + threadIdx.x;
    int v = (i < NN) ? g_cnt[i] : 0;
    sm[threadIdx.x] = v;
    __syncthreads();
#pragma unroll
    for (int off = 1; off < 1024; off <<= 1) {
        int t = (threadIdx.x >= off) ? sm[threadIdx.x - off] : 0;
        __syncthreads();
        sm[threadIdx.x] += t;
        __syncthreads();
    }
    if (i < NN) g_row[i] = sm[threadIdx.x] - v;
    if (threadIdx.x == 1023) g_bsum[blockIdx.x] = sm[1023];
}

__global__ void k_scan2(int nb) {
    int t = threadIdx.x;
    int v = (t < nb) ? g_bsum[t] : 0;
    int lane = t & 31, w = t >> 5;
    int x = v;
#pragma unroll
    for (int off = 1; off < 32; off <<= 1) {
        int y = __shfl_up_sync(0xffffffffu, x, off);
        if (lane >= off) x += y;
    }
    __shared__ int ws[2];
    if (lane == 31) ws[w] = x;
    __syncthreads();
    if (w == 1) x += ws[0];
    if (t < nb) g_bsum[t] = x - v;   // exclusive
}

__global__ void k_scan3() {
    int i = blockIdx.x * blockDim.x + threadIdx.x;
    if (i < NN) {
        int v = g_row[i] + g_bsum[i >> 10];
        g_row[i] = v;
        g_pos[i] = v;
    }
}

__global__ void k_scatter(const int* __restrict__ src, const int* __restrict__ dst) {
    int e = blockIdx.x * blockDim.x + threadIdx.x;
    if (e < EE) {
        int d = dst[e];
        int p = atomicAdd(&g_pos[d], 1);
        g_csr_src[p] = src[e];
    }
}

// -------------------- fused GEMM + el/er + fp16 emit ------------------------
// Wd layout: Wd[k][c][tx] duplicated pair -> thread tx loads its splat for
// column (tx*4+c) as ONE conflict-free LDS.64 (no movs in the mainloop).
struct GSm {
    union {
        struct {
            float Xs[GTK][GTM + 2];          // 8448 B (transposed, padded)
            float2 Wd[GTK][4][32];           // 32768 B duplicated W
        } ml;
        __half Hs[GTM][FDIM];                // 16384 B epilogue staging
    } u;
};

__global__ void __launch_bounds__(256) k_gemm_fused(const float* __restrict__ X,
                                                    const float* __restrict__ W,
                                                    const float* __restrict__ al,
                                                    const float* __restrict__ ar) {
    __shared__ GSm sm;
    int t = threadIdx.x;
    int tx = t & 31, ty = t >> 5;
    int row0 = blockIdx.x * GTM;

    ull acc[4][4];
#pragma unroll
    for (int p = 0; p < 4; p++)
#pragma unroll
        for (int c = 0; c < 4; c++) acc[p][c] = 0ull;

    for (int kc = 0; kc < FDIM; kc += GTK) {
#pragma unroll
        for (int i = 0; i < 8; i++) {
            int id = t + i * 256;
            int r = id >> 5, c = id & 31;            // r = tile row, c = k
            int gr = row0 + r;
            sm.u.ml.Xs[c][r] = (gr < NN) ? X[gr * FDIM + kc + c] : 0.f;
        }
#pragma unroll
        for (int i = 0; i < 16; i++) {
            int id = t + i * 256;
            int r = id >> 7, col = id & 127;         // r = k, col = output col
            float w = W[(kc + r) * FDIM + col];
            sm.u.ml.Wd[r][col & 3][col >> 2] = make_float2(w, w);
        }
        __syncthreads();
#pragma unroll
        for (int k = 0; k < GTK; k++) {
            ull b0 = *reinterpret_cast<const ull*>(&sm.u.ml.Wd[k][0][tx]);
            ull b1 = *reinterpret_cast<const ull*>(&sm.u.ml.Wd[k][1][tx]);
            ull b2 = *reinterpret_cast<const ull*>(&sm.u.ml.Wd[k][2][tx]);
            ull b3 = *reinterpret_cast<const ull*>(&sm.u.ml.Wd[k][3][tx]);
#pragma unroll
            for (int p = 0; p < 4; p++) {
                ull a = *reinterpret_cast<const ull*>(&sm.u.ml.Xs[k][ty * 8 + p * 2]);
                ffma2(acc[p][0], a, b0);
                ffma2(acc[p][1], a, b1);
                ffma2(acc[p][2], a, b2);
                ffma2(acc[p][3], a, b3);
            }
        }
        __syncthreads();
    }

    // epilogue: fp16 emit (head-interleaved) + el/er partial dots
    float4 alv = *reinterpret_cast<const float4*>(&al[tx * 4]);
    float4 arv = *reinterpret_cast<const float4*>(&ar[tx * 4]);
    int head = tx >> 3;
#pragma unroll
    for (int p = 0; p < 4; p++) {
        float2 v0 = unpk(acc[p][0]);
        float2 v1 = unpk(acc[p][1]);
        float2 v2 = unpk(acc[p][2]);
        float2 v3 = unpk(acc[p][3]);
        int r0 = ty * 8 + p * 2, r1 = r0 + 1;
#pragma unroll
        for (int c = 0; c < 4; c++) {
            int col = tx * 4 + c;
            int pos = ((col & 31) << 2) | (col >> 5);   // head-interleave
            float lo = (c == 0) ? v0.x : (c == 1) ? v1.x : (c == 2) ? v2.x : v3.x;
            float hi = (c == 0) ? v0.y : (c == 1) ? v1.y : (c == 2) ? v2.y : v3.y;
            sm.u.Hs[r0][pos] = __float2half(lo);
            sm.u.Hs[r1][pos] = __float2half(hi);
        }
        float pl0 = v0.x * alv.x + v1.x * alv.y + v2.x * alv.z + v3.x * alv.w;
        float pr0 = v0.x * arv.x + v1.x * arv.y + v2.x * arv.z + v3.x * arv.w;
        float pl1 = v0.y * alv.x + v1.y * alv.y + v2.y * alv.z + v3.y * alv.w;
        float pr1 = v0.y * arv.x + v1.y * arv.y + v2.y * arv.z + v3.y * arv.w;
#pragma unroll
        for (int off = 4; off; off >>= 1) {
            pl0 += __shfl_xor_sync(0xffffffffu, pl0, off);
            pr0 += __shfl_xor_sync(0xffffffffu, pr0, off);
            pl1 += __shfl_xor_sync(0xffffffffu, pl1, off);
            pr1 += __shfl_xor_sync(0xffffffffu, pr1, off);
        }
        if ((tx & 7) == 0) {
            if (row0 + r0 < NN) {
                g_el[(row0 + r0) * 4 + head] = pl0;
                g_er[(row0 + r0) * 4 + head] = pr0;
            }
            if (row0 + r1 < NN) {
                g_el[(row0 + r1) * 4 + head] = pl1;
                g_er[(row0 + r1) * 4 + head] = pr1;
            }
        }
    }
    __syncthreads();   // Hs fully written (aliases mainloop smem, now dead)
#pragma unroll
    for (int i = t; i < GTM * 16; i += 256) {
        int r = i >> 4, c = i & 15;
        int gr = row0 + r;
        if (gr < NN)
            reinterpret_cast<uint4*>(g_feat_h + (size_t)gr * FDIM)[c] =
                reinterpret_cast<const uint4*>(&sm.u.Hs[r][0])[c];
    }
}

// -------------------- single-pass warp-per-node softmax + SpMM --------------
#define AGG_WARPS 8

// MODE 1: layer1 -> elu, 128 feats (fp32) to g_h1. MODE 2: head-mean to out.
template <int MODE>
__global__ void __launch_bounds__(AGG_WARPS * 32) k_agg(const float* __restrict__ resid,
                                                        const float* __restrict__ bias,
                                                        float* __restrict__ out) {
    __shared__ __align__(16) float4 sm_w[AGG_WARPS][33];
    __shared__ int sm_s[AGG_WARPS][32];

    int wid  = threadIdx.x >> 5;
    int lane = threadIdx.x & 31;
    int node = blockIdx.x * AGG_WARPS + wid;
    if (node >= NN) return;

    int base = g_row[node];
    int deg  = g_cnt[node];
    float4 er4 = reinterpret_cast<const float4*>(g_er)[node];

    float sx = 0.f, sy = 0.f, sz = 0.f, sw = 0.f;
    float a0 = 0.f, a1 = 0.f, a2 = 0.f, a3 = 0.f;

    for (int c0 = 0; c0 < deg; c0 += 32) {
        int m = deg - c0; if (m > 32) m = 32;
        if (lane < m) {
            int s = g_csr_src[base + c0 + lane];
            float4 l4 = reinterpret_cast<const float4*>(g_el)[s];
            float4 w4;
            w4.x = __expf(lrelu(l4.x + er4.x));
            w4.y = __expf(lrelu(l4.y + er4.y));
            w4.z = __expf(lrelu(l4.z + er4.z));
            w4.w = __expf(lrelu(l4.w + er4.w));
            sx += w4.x; sy += w4.y; sz += w4.z; sw += w4.w;
            sm_s[wid][lane] = s;
            sm_w[wid][lane] = w4;
        }
        __syncwarp();
        int j = 0;
        for (; j + 3 < m; j += 4) {
            int   s0 = sm_s[wid][j];
            int   s1 = sm_s[wid][j + 1];
            int   s2 = sm_s[wid][j + 2];
            int   s3 = sm_s[wid][j + 3];
            float4 w0 = sm_w[wid][j];
            float4 w1 = sm_w[wid][j + 1];
            float4 w2 = sm_w[wid][j + 2];
            float4 w3 = sm_w[wid][j + 3];
            uint2 u0 = *reinterpret_cast<const uint2*>(g_feat_h + (size_t)s0 * FDIM + lane * 4);
            uint2 u1 = *reinterpret_cast<const uint2*>(g_feat_h + (size_t)s1 * FDIM + lane * 4);
            uint2 u2 = *reinterpret_cast<const uint2*>(g_feat_h + (size_t)s2 * FDIM + lane * 4);
            uint2 u3 = *reinterpret_cast<const uint2*>(g_feat_h + (size_t)s3 * FDIM + lane * 4);
            float2 f00 = __half22float2(*reinterpret_cast<__half2*>(&u0.x));
            float2 f01 = __half22float2(*reinterpret_cast<__half2*>(&u0.y));
            float2 f10 = __half22float2(*reinterpret_cast<__half2*>(&u1.x));
            float2 f11 = __half22float2(*reinterpret_cast<__half2*>(&u1.y));
            float2 f20 = __half22float2(*reinterpret_cast<__half2*>(&u2.x));
            float2 f21 = __half22float2(*reinterpret_cast<__half2*>(&u2.y));
            float2 f30 = __half22float2(*reinterpret_cast<__half2*>(&u3.x));
            float2 f31 = __half22float2(*reinterpret_cast<__half2*>(&u3.y));
            a0 += w0.x * f00.x + w1.x * f10.x + w2.x * f20.x + w3.x * f30.x;
            a1 += w0.y * f00.y + w1.y * f10.y + w2.y * f20.y + w3.y * f30.y;
            a2 += w0.z * f01.x + w1.z * f11.x + w2.z * f21.x + w3.z * f31.x;
            a3 += w0.w * f01.y + w1.w * f11.y + w2.w * f21.y + w3.w * f31.y;
        }
        for (; j < m; j++) {
            int   s0 = sm_s[wid][j];
            float4 w0 = sm_w[wid][j];
            uint2 u0 = *reinterpret_cast<const uint2*>(g_feat_h + (size_t)s0 * FDIM + lane * 4);
            float2 f00 = __half22float2(*reinterpret_cast<__half2*>(&u0.x));
            float2 f01 = __half22float2(*reinterpret_cast<__half2*>(&u0.y));
            a0 += w0.x * f00.x;
            a1 += w0.y * f00.y;
            a2 += w0.z * f01.x;
            a3 += w0.w * f01.y;
        }
        __syncwarp();
    }

#pragma unroll
    for (int off = 16; off; off >>= 1) {
        sx += __shfl_xor_sync(0xffffffffu, sx, off);
        sy += __shfl_xor_sync(0xffffffffu, sy, off);
        sz += __shfl_xor_sync(0xffffffffu, sz, off);
        sw += __shfl_xor_sync(0xffffffffu, sw, off);
    }
    float invx = 1.f / fmaxf(sx, 1e-9f);
    float invy = 1.f / fmaxf(sy, 1e-9f);
    float invz = 1.f / fmaxf(sz, 1e-9f);
    float invw = 1.f / fmaxf(sw, 1e-9f);

    float r0 = a0 * invx + resid[node * FDIM + 0  + lane] + bias[0  + lane];
    float r1 = a1 * invy + resid[node * FDIM + 32 + lane] + bias[32 + lane];
    float r2 = a2 * invz + resid[node * FDIM + 64 + lane] + bias[64 + lane];
    float r3 = a3 * invw + resid[node * FDIM + 96 + lane] + bias[96 + lane];

    if (MODE == 1) {
        out[node * FDIM + 0  + lane] = elu1(r0);
        out[node * FDIM + 32 + lane] = elu1(r1);
        out[node * FDIM + 64 + lane] = elu1(r2);
        out[node * FDIM + 96 + lane] = elu1(r3);
    } else {
        out[node * 32 + lane] = 0.25f * (r0 + r1 + r2 + r3);
    }
}

// -------------------- launch ------------------------------------------------
extern "C" void kernel_launch(void* const* d_in, const int* in_sizes, int n_in,
                              void* d_out, int out_size) {
    const float* x   = (const float*)d_in[0];
    const float* W1  = (const float*)d_in[1];
    const float* al1 = (const float*)d_in[2];
    const float* ar1 = (const float*)d_in[3];
    const float* b1  = (const float*)d_in[4];
    const float* W2  = (const float*)d_in[5];
    const float* al2 = (const float*)d_in[6];
    const float* ar2 = (const float*)d_in[7];
    const float* b2  = (const float*)d_in[8];
    const int*   src = (const int*)d_in[9];
    const int*   dst = (const int*)d_in[10];
    float* out = (float*)d_out;

    float* h1 = nullptr;
    cudaGetSymbolAddress((void**)&h1, g_h1);

    const int TB = 256;
    int nblkN = (NN + TB - 1) / TB;
    int nblkE = (EE + TB - 1) / TB;
    int nScan = (NN + 1023) / 1024;                 // 49
    int nAgg  = (NN + AGG_WARPS - 1) / AGG_WARPS;   // 6250
    int nGemm = (NN + GTM - 1) / GTM;               // 782

    // Launch order: layer-1 GEMM placed 4th (no CSR dependency) so the
    // ncu capture slot lands on it next round.
    k_zero_cnt<<<nblkN, TB>>>();                    // 1
    k_count<<<nblkE, TB>>>(dst);                    // 2
    k_scan1<<<nScan, 1024>>>();                     // 3
    k_gemm_fused<<<nGemm, 256>>>(x, W1, al1, ar1);  // 4  <- profiled
    k_scan2<<<1, 64>>>(nScan);                      // 5
    k_scan3<<<nblkN, TB>>>();                       // 6
    k_scatter<<<nblkE, TB>>>(src, dst);             // 7
    k_agg<1><<<nAgg, AGG_WARPS * 32>>>(x, b1, h1);  // 8
    k_gemm_fused<<<nGemm, 256>>>(h1, W2, al2, ar2); // 9
    k_agg<2><<<nAgg, AGG_WARPS * 32>>>(h1, b2, out);// 10
}

// round 10
// speedup vs baseline: 1.2605x; 1.2605x over previous
#include <cuda_runtime.h>
#include <cuda_fp16.h>
#include <cuda_bf16.h>

// ---------------------------------------------------------------------------
// GAT (2-layer, H=4, D=32, IN=128) on GB300, round 9.
//  - GEMM moved to tensor cores: fp16 HMMA mma.sync.m16n8k16, fp32 accum,
//    128x128x128 tile per block, ldmatrix from padded smem (conflict-free).
//  - el/er + head-interleaved fp16 feature emit fused in the epilogue.
//  - CSR build + single-pass warp-per-node agg = R4 structure (best known).
// ---------------------------------------------------------------------------

#define NN 50000
#define EE 800000
#define FDIM 128
#define NEG_SLOPE 0.2f
#define MB 128                 // GEMM rows per block
#define KPAD 136               // padded smem row (halves); 272B stride

typedef unsigned long long ull;

// -------------------- scratch (static device globals) ----------------------
__device__ __half g_feat_h[NN * FDIM];   // 12.8 MB fp16 features, head-interleaved
__device__ float  g_h1[NN * FDIM];       // 25.6 MB layer-1 output
__device__ int    g_csr_src[EE];         //  3.2 MB
__device__ int    g_cnt[NN];
__device__ int    g_row[NN];
__device__ int    g_pos[NN];
__device__ float  g_el[NN * 4];
__device__ float  g_er[NN * 4];
__device__ int    g_bsum[64];

// -------------------- math helpers ------------------------------------------
__device__ __forceinline__ float lrelu(float x) { return x > 0.f ? x : NEG_SLOPE * x; }
__device__ __forceinline__ float elu1(float x)  { return x > 0.f ? x : (__expf(x) - 1.f); }

__device__ __forceinline__ unsigned smaddr(const void* p) {
    return (unsigned)__cvta_generic_to_shared(p);
}
__device__ __forceinline__ void ldsm_x4(unsigned* r, unsigned addr) {
    asm volatile("ldmatrix.sync.aligned.m8n8.x4.shared.b16 {%0,%1,%2,%3}, [%4];"
                 : "=r"(r[0]), "=r"(r[1]), "=r"(r[2]), "=r"(r[3]) : "r"(addr));
}
__device__ __forceinline__ void ldsm_x4_t(unsigned* r, unsigned addr) {
    asm volatile("ldmatrix.sync.aligned.m8n8.x4.trans.shared.b16 {%0,%1,%2,%3}, [%4];"
                 : "=r"(r[0]), "=r"(r[1]), "=r"(r[2]), "=r"(r[3]) : "r"(addr));
}
__device__ __forceinline__ void mma16816(float* d, const unsigned* a, const unsigned* b) {
    asm volatile("mma.sync.aligned.m16n8k16.row.col.f32.f16.f16.f32 "
                 "{%0,%1,%2,%3}, {%4,%5,%6,%7}, {%8,%9}, {%0,%1,%2,%3};"
                 : "+f"(d[0]), "+f"(d[1]), "+f"(d[2]), "+f"(d[3])
                 : "r"(a[0]), "r"(a[1]), "r"(a[2]), "r"(a[3]), "r"(b[0]), "r"(b[1]));
}

// -------------------- CSR build --------------------------------------------
__global__ void k_zero_cnt() {
    int i = blockIdx.x * blockDim.x + threadIdx.x;
    if (i < NN) g_cnt[i] = 0;
}

__global__ void k_count(const int* __restrict__ dst) {
    int e = blockIdx.x * blockDim.x + threadIdx.x;
    if (e < EE) atomicAdd(&g_cnt[dst[e]], 1);
}

__global__ void k_scan1() {
    __shared__ int sm[1024];
    int i = blockIdx.x * 1024 + threadIdx.x;
    int v = (i < NN) ? g_cnt[i] : 0;
    sm[threadIdx.x] = v;
    __syncthreads();
#pragma unroll
    for (int off = 1; off < 1024; off <<= 1) {
        int t = (threadIdx.x >= off) ? sm[threadIdx.x - off] : 0;
        __syncthreads();
        sm[threadIdx.x] += t;
        __syncthreads();
    }
    if (i < NN) g_row[i] = sm[threadIdx.x] - v;
    if (threadIdx.x == 1023) g_bsum[blockIdx.x] = sm[1023];
}

__global__ void k_scan2(int nb) {
    int t = threadIdx.x;
    int v = (t < nb) ? g_bsum[t] : 0;
    int lane = t & 31, w = t >> 5;
    int x = v;
#pragma unroll
    for (int off = 1; off < 32; off <<= 1) {
        int y = __shfl_up_sync(0xffffffffu, x, off);
        if (lane >= off) x += y;
    }
    __shared__ int ws[2];
    if (lane == 31) ws[w] = x;
    __syncthreads();
    if (w == 1) x += ws[0];
    if (t < nb) g_bsum[t] = x - v;   // exclusive
}

__global__ void k_scan3() {
    int i = blockIdx.x * blockDim.x + threadIdx.x;
    if (i < NN) {
        int v = g_row[i] + g_bsum[i >> 10];
        g_row[i] = v;
        g_pos[i] = v;
    }
}

__global__ void k_scatter(const int* __restrict__ src, const int* __restrict__ dst) {
    int e = blockIdx.x * blockDim.x + threadIdx.x;
    if (e < EE) {
        int d = dst[e];
        int p = atomicAdd(&g_pos[d], 1);
        g_csr_src[p] = src[e];
    }
}

// -------------------- tensor-core GEMM + el/er + fp16 emit ------------------
// Y = X[N,128] @ W[128,128] in fp16 HMMA, fp32 accum.
// 8 warps: wm = wid&3 (rows 32*wm..+31), wn = wid>>2 (cols 64*wn..+63).
__global__ void __launch_bounds__(256) k_gemm_fused(const float* __restrict__ X,
                                                    const float* __restrict__ W,
                                                    const float* __restrict__ al,
                                                    const float* __restrict__ ar) {
    __shared__ __half Xp[MB][KPAD];      // 34816 B ; epilogue reuses as Hs
    __shared__ __half Wp[FDIM][KPAD];    // 34816 B

    int t = threadIdx.x;
    int lane = t & 31, wid = t >> 5;
    int row0 = blockIdx.x * MB;

    // ---- fill smem (f32 -> f16) ----
    for (int i = t; i < MB * 32; i += 256) {            // 16 iters
        int r = i >> 5, c4 = (i & 31) * 4;
        int gr = row0 + r;
        float4 v = (gr < NN) ? *reinterpret_cast<const float4*>(&X[gr * FDIM + c4])
                             : make_float4(0.f, 0.f, 0.f, 0.f);
        *reinterpret_cast<__half2*>(&Xp[r][c4])     = __floats2half2_rn(v.x, v.y);
        *reinterpret_cast<__half2*>(&Xp[r][c4 + 2]) = __floats2half2_rn(v.z, v.w);
    }
    for (int i = t; i < FDIM * 32; i += 256) {
        int r = i >> 5, c4 = (i & 31) * 4;
        float4 v = *reinterpret_cast<const float4*>(&W[r * FDIM + c4]);
        *reinterpret_cast<__half2*>(&Wp[r][c4])     = __floats2half2_rn(v.x, v.y);
        *reinterpret_cast<__half2*>(&Wp[r][c4 + 2]) = __floats2half2_rn(v.z, v.w);
    }
    __syncthreads();

    int wm = wid & 3, wn = wid >> 2;
    float acc[2][8][4];
#pragma unroll
    for (int t2 = 0; t2 < 2; t2++)
#pragma unroll
        for (int u = 0; u < 8; u++)
#pragma unroll
            for (int c = 0; c < 4; c++) acc[t2][u][c] = 0.f;

    // ---- mainloop: 8 k16 steps ----
#pragma unroll
    for (int kk = 0; kk < 8; kk++) {
        unsigned A0[4], A1[4];
        {
            int r = wm * 32 + (lane & 15);
            int k = kk * 16 + ((lane >> 4) & 1) * 8;
            ldsm_x4(A0, smaddr(&Xp[r][k]));
            ldsm_x4(A1, smaddr(&Xp[r + 16][k]));
        }
        unsigned B[8][2];
#pragma unroll
        for (int ub = 0; ub < 4; ub++) {
            int kloc = kk * 16 + (lane & 7) + ((lane >> 3) & 1) * 8;
            int col = wn * 64 + (ub * 2 + ((lane >> 4) & 1)) * 8;
            unsigned r4[4];
            ldsm_x4_t(r4, smaddr(&Wp[kloc][col]));
            B[2 * ub][0] = r4[0]; B[2 * ub][1] = r4[1];
            B[2 * ub + 1][0] = r4[2]; B[2 * ub + 1][1] = r4[3];
        }
#pragma unroll
        for (int u = 0; u < 8; u++) {
            mma16816(acc[0][u], A0, B[u]);
            mma16816(acc[1][u], A1, B[u]);
        }
    }
    __syncthreads();   // all reads of Xp/Wp done before Hs overwrite

    // ---- epilogue: head-interleaved fp16 emit into Hs (= Xp) ----
    __half (*Hs)[KPAD] = Xp;
#pragma unroll
    for (int t2 = 0; t2 < 2; t2++) {
#pragma unroll
        for (int u = 0; u < 8; u++) {
            int R = wm * 32 + t2 * 16 + (lane >> 2);
            int C = wn * 64 + u * 8 + (lane & 3) * 2;
            int p0 = ((C & 31) << 2) | (C >> 5);           // head-interleave
            Hs[R][p0]         = __float2half(acc[t2][u][0]);
            Hs[R][p0 + 4]     = __float2half(acc[t2][u][1]);
            Hs[R + 8][p0]     = __float2half(acc[t2][u][2]);
            Hs[R + 8][p0 + 4] = __float2half(acc[t2][u][3]);
        }
    }
    __syncthreads();

    // ---- el/er from staged features: warp wid handles rows wid*16..+15 ----
    float alv[4], arv[4];
#pragma unroll
    for (int h = 0; h < 4; h++) {
        alv[h] = al[h * 32 + lane];
        arv[h] = ar[h * 32 + lane];
    }
    for (int i = 0; i < 16; i++) {
        int R = wid * 16 + i;
        int gr = row0 + R;
        uint2 uu = *reinterpret_cast<const uint2*>(&Hs[R][lane * 4]);
        float2 q0 = __half22float2(*reinterpret_cast<__half2*>(&uu.x));
        float2 q1 = __half22float2(*reinterpret_cast<__half2*>(&uu.y));
        float v0 = q0.x, v1 = q0.y, v2 = q1.x, v3 = q1.y;
        float l0 = v0 * alv[0], l1 = v1 * alv[1], l2 = v2 * alv[2], l3 = v3 * alv[3];
        float r0 = v0 * arv[0], r1 = v1 * arv[1], r2 = v2 * arv[2], r3 = v3 * arv[3];
#pragma unroll
        for (int off = 16; off; off >>= 1) {
            l0 += __shfl_xor_sync(0xffffffffu, l0, off);
            l1 += __shfl_xor_sync(0xffffffffu, l1, off);
            l2 += __shfl_xor_sync(0xffffffffu, l2, off);
            l3 += __shfl_xor_sync(0xffffffffu, l3, off);
            r0 += __shfl_xor_sync(0xffffffffu, r0, off);
            r1 += __shfl_xor_sync(0xffffffffu, r1, off);
            r2 += __shfl_xor_sync(0xffffffffu, r2, off);
            r3 += __shfl_xor_sync(0xffffffffu, r3, off);
        }
        if (lane == 0 && gr < NN) {
            g_el[gr * 4 + 0] = l0; g_el[gr * 4 + 1] = l1;
            g_el[gr * 4 + 2] = l2; g_el[gr * 4 + 3] = l3;
            g_er[gr * 4 + 0] = r0; g_er[gr * 4 + 1] = r1;
            g_er[gr * 4 + 2] = r2; g_er[gr * 4 + 3] = r3;
        }
    }

    // ---- coalesced fp16 feature write-out (16B chunks) ----
    for (int i = t; i < MB * 16; i += 256) {
        int r = i >> 4, c = i & 15;
        int gr = row0 + r;
        if (gr < NN)
            reinterpret_cast<uint4*>(g_feat_h + (size_t)gr * FDIM)[c] =
                *reinterpret_cast<const uint4*>(&Hs[r][c * 8]);
    }
}

// -------------------- single-pass warp-per-node softmax + SpMM --------------
#define AGG_WARPS 8

// MODE 1: layer1 -> elu, 128 feats (fp32) to g_h1. MODE 2: head-mean to out.
template <int MODE>
__global__ void __launch_bounds__(AGG_WARPS * 32) k_agg(const float* __restrict__ resid,
                                                        const float* __restrict__ bias,
                                                        float* __restrict__ out) {
    __shared__ __align__(16) float4 sm_w[AGG_WARPS][33];
    __shared__ int sm_s[AGG_WARPS][32];

    int wid  = threadIdx.x >> 5;
    int lane = threadIdx.x & 31;
    int node = blockIdx.x * AGG_WARPS + wid;
    if (node >= NN) return;

    int base = g_row[node];
    int deg  = g_cnt[node];
    float4 er4 = reinterpret_cast<const float4*>(g_er)[node];

    float sx = 0.f, sy = 0.f, sz = 0.f, sw = 0.f;
    float a0 = 0.f, a1 = 0.f, a2 = 0.f, a3 = 0.f;

    for (int c0 = 0; c0 < deg; c0 += 32) {
        int m = deg - c0; if (m > 32) m = 32;
        if (lane < m) {
            int s = g_csr_src[base + c0 + lane];
            float4 l4 = reinterpret_cast<const float4*>(g_el)[s];
            float4 w4;
            w4.x = __expf(lrelu(l4.x + er4.x));
            w4.y = __expf(lrelu(l4.y + er4.y));
            w4.z = __expf(lrelu(l4.z + er4.z));
            w4.w = __expf(lrelu(l4.w + er4.w));
            sx += w4.x; sy += w4.y; sz += w4.z; sw += w4.w;
            sm_s[wid][lane] = s;
            sm_w[wid][lane] = w4;
        }
        __syncwarp();
        int j = 0;
        for (; j + 3 < m; j += 4) {
            int   s0 = sm_s[wid][j];
            int   s1 = sm_s[wid][j + 1];
            int   s2 = sm_s[wid][j + 2];
            int   s3 = sm_s[wid][j + 3];
            float4 w0 = sm_w[wid][j];
            float4 w1 = sm_w[wid][j + 1];
            float4 w2 = sm_w[wid][j + 2];
            float4 w3 = sm_w[wid][j + 3];
            uint2 u0 = *reinterpret_cast<const uint2*>(g_feat_h + (size_t)s0 * FDIM + lane * 4);
            uint2 u1 = *reinterpret_cast<const uint2*>(g_feat_h + (size_t)s1 * FDIM + lane * 4);
            uint2 u2 = *reinterpret_cast<const uint2*>(g_feat_h + (size_t)s2 * FDIM + lane * 4);
            uint2 u3 = *reinterpret_cast<const uint2*>(g_feat_h + (size_t)s3 * FDIM + lane * 4);
            float2 f00 = __half22float2(*reinterpret_cast<__half2*>(&u0.x));
            float2 f01 = __half22float2(*reinterpret_cast<__half2*>(&u0.y));
            float2 f10 = __half22float2(*reinterpret_cast<__half2*>(&u1.x));
            float2 f11 = __half22float2(*reinterpret_cast<__half2*>(&u1.y));
            float2 f20 = __half22float2(*reinterpret_cast<__half2*>(&u2.x));
            float2 f21 = __half22float2(*reinterpret_cast<__half2*>(&u2.y));
            float2 f30 = __half22float2(*reinterpret_cast<__half2*>(&u3.x));
            float2 f31 = __half22float2(*reinterpret_cast<__half2*>(&u3.y));
            a0 += w0.x * f00.x + w1.x * f10.x + w2.x * f20.x + w3.x * f30.x;
            a1 += w0.y * f00.y + w1.y * f10.y + w2.y * f20.y + w3.y * f30.y;
            a2 += w0.z * f01.x + w1.z * f11.x + w2.z * f21.x + w3.z * f31.x;
            a3 += w0.w * f01.y + w1.w * f11.y + w2.w * f21.y + w3.w * f31.y;
        }
        for (; j < m; j++) {
            int   s0 = sm_s[wid][j];
            float4 w0 = sm_w[wid][j];
            uint2 u0 = *reinterpret_cast<const uint2*>(g_feat_h + (size_t)s0 * FDIM + lane * 4);
            float2 f00 = __half22float2(*reinterpret_cast<__half2*>(&u0.x));
            float2 f01 = __half22float2(*reinterpret_cast<__half2*>(&u0.y));
            a0 += w0.x * f00.x;
            a1 += w0.y * f00.y;
            a2 += w0.z * f01.x;
            a3 += w0.w * f01.y;
        }
        __syncwarp();
    }

#pragma unroll
    for (int off = 16; off; off >>= 1) {
        sx += __shfl_xor_sync(0xffffffffu, sx, off);
        sy += __shfl_xor_sync(0xffffffffu, sy, off);
        sz += __shfl_xor_sync(0xffffffffu, sz, off);
        sw += __shfl_xor_sync(0xffffffffu, sw, off);
    }
    float invx = 1.f / fmaxf(sx, 1e-9f);
    float invy = 1.f / fmaxf(sy, 1e-9f);
    float invz = 1.f / fmaxf(sz, 1e-9f);
    float invw = 1.f / fmaxf(sw, 1e-9f);

    float r0 = a0 * invx + resid[node * FDIM + 0  + lane] + bias[0  + lane];
    float r1 = a1 * invy + resid[node * FDIM + 32 + lane] + bias[32 + lane];
    float r2 = a2 * invz + resid[node * FDIM + 64 + lane] + bias[64 + lane];
    float r3 = a3 * invw + resid[node * FDIM + 96 + lane] + bias[96 + lane];

    if (MODE == 1) {
        out[node * FDIM + 0  + lane] = elu1(r0);
        out[node * FDIM + 32 + lane] = elu1(r1);
        out[node * FDIM + 64 + lane] = elu1(r2);
        out[node * FDIM + 96 + lane] = elu1(r3);
    } else {
        out[node * 32 + lane] = 0.25f * (r0 + r1 + r2 + r3);
    }
}

// -------------------- launch ------------------------------------------------
extern "C" void kernel_launch(void* const* d_in, const int* in_sizes, int n_in,
                              void* d_out, int out_size) {
    const float* x   = (const float*)d_in[0];
    const float* W1  = (const float*)d_in[1];
    const float* al1 = (const float*)d_in[2];
    const float* ar1 = (const float*)d_in[3];
    const float* b1  = (const float*)d_in[4];
    const float* W2  = (const float*)d_in[5];
    const float* al2 = (const float*)d_in[6];
    const float* ar2 = (const float*)d_in[7];
    const float* b2  = (const float*)d_in[8];
    const int*   src = (const int*)d_in[9];
    const int*   dst = (const int*)d_in[10];
    float* out = (float*)d_out;

    float* h1 = nullptr;
    cudaGetSymbolAddress((void**)&h1, g_h1);

    const int TB = 256;
    int nblkN = (NN + TB - 1) / TB;
    int nblkE = (EE + TB - 1) / TB;
    int nScan = (NN + 1023) / 1024;                 // 49
    int nAgg  = (NN + AGG_WARPS - 1) / AGG_WARPS;   // 6250
    int nGemm = (NN + MB - 1) / MB;                 // 391

    // layer-1 GEMM stays at launch slot 4 (profiled slot).
    k_zero_cnt<<<nblkN, TB>>>();                    // 1
    k_count<<<nblkE, TB>>>(dst);                    // 2
    k_scan1<<<nScan, 1024>>>();                     // 3
    k_gemm_fused<<<nGemm, 256>>>(x, W1, al1, ar1);  // 4  <- profiled
    k_scan2<<<1, 64>>>(nScan);                      // 5
    k_scan3<<<nblkN, TB>>>();                       // 6
    k_scatter<<<nblkE, TB>>>(src, dst);             // 7
    k_agg<1><<<nAgg, AGG_WARPS * 32>>>(x, b1, h1);  // 8
    k_gemm_fused<<<nGemm, 256>>>(h1, W2, al2, ar2); // 9
    k_agg<2><<<nAgg, AGG_WARPS * 32>>>(h1, b2, out);// 10
}

// round 11
// speedup vs baseline: 1.4467x; 1.1477x over previous
#include <cuda_runtime.h>
#include <cuda_fp16.h>
#include <cuda_bf16.h>

// ---------------------------------------------------------------------------
// GAT (2-layer, H=4, D=32, IN=128) on GB300, round 11.
//  - HMMA GEMM retuned: MB=64 tile (acc regs halved), W pre-converted to fp16
//    in gmem by k_wconv (GEMM fill = pure copies), __launch_bounds__(256,3)
//    -> ~3 blocks/SM co-resident (was 2 @ 70KB smem / 100 regs).
//  - el/er + head-interleaved fp16 feature emit fused in epilogue (unchanged).
//  - CSR build + single-pass warp-per-node agg (unchanged, best known).
// ---------------------------------------------------------------------------

#define NN 50000
#define EE 800000
#define FDIM 128
#define NEG_SLOPE 0.2f
#define MB 64                  // GEMM rows per block
#define KPAD 136               // padded smem row (halves); 272B stride (16B mult.)

typedef unsigned long long ull;

// -------------------- scratch (static device globals) ----------------------
__device__ __half g_feat_h[NN * FDIM];   // 12.8 MB fp16 features, head-interleaved
__device__ float  g_h1[NN * FDIM];       // 25.6 MB layer-1 output
__device__ __half g_Wh[2][FDIM * FDIM];  // 64 KB   fp16 weights (pre-converted)
__device__ int    g_csr_src[EE];         //  3.2 MB
__device__ int    g_cnt[NN];
__device__ int    g_row[NN];
__device__ int    g_pos[NN];
__device__ float  g_el[NN * 4];
__device__ float  g_er[NN * 4];
__device__ int    g_bsum[64];

// -------------------- math helpers ------------------------------------------
__device__ __forceinline__ float lrelu(float x) { return x > 0.f ? x : NEG_SLOPE * x; }
__device__ __forceinline__ float elu1(float x)  { return x > 0.f ? x : (__expf(x) - 1.f); }

__device__ __forceinline__ unsigned smaddr(const void* p) {
    return (unsigned)__cvta_generic_to_shared(p);
}
__device__ __forceinline__ void ldsm_x4(unsigned* r, unsigned addr) {
    asm volatile("ldmatrix.sync.aligned.m8n8.x4.shared.b16 {%0,%1,%2,%3}, [%4];"
                 : "=r"(r[0]), "=r"(r[1]), "=r"(r[2]), "=r"(r[3]) : "r"(addr));
}
__device__ __forceinline__ void ldsm_x4_t(unsigned* r, unsigned addr) {
    asm volatile("ldmatrix.sync.aligned.m8n8.x4.trans.shared.b16 {%0,%1,%2,%3}, [%4];"
                 : "=r"(r[0]), "=r"(r[1]), "=r"(r[2]), "=r"(r[3]) : "r"(addr));
}
__device__ __forceinline__ void mma16816(float* d, const unsigned* a, const unsigned* b) {
    asm volatile("mma.sync.aligned.m16n8k16.row.col.f32.f16.f16.f32 "
                 "{%0,%1,%2,%3}, {%4,%5,%6,%7}, {%8,%9}, {%0,%1,%2,%3};"
                 : "+f"(d[0]), "+f"(d[1]), "+f"(d[2]), "+f"(d[3])
                 : "r"(a[0]), "r"(a[1]), "r"(a[2]), "r"(a[3]), "r"(b[0]), "r"(b[1]));
}

// -------------------- weight pre-convert ------------------------------------
__global__ void k_wconv(const float* __restrict__ W, int slot) {
    int i = blockIdx.x * blockDim.x + threadIdx.x;      // over 4096 float4
    if (i >= FDIM * FDIM / 4) return;
    float4 v = reinterpret_cast<const float4*>(W)[i];
    __half2 h0 = __floats2half2_rn(v.x, v.y);
    __half2 h1 = __floats2half2_rn(v.z, v.w);
    reinterpret_cast<__half2*>(g_Wh[slot])[i * 2]     = h0;
    reinterpret_cast<__half2*>(g_Wh[slot])[i * 2 + 1] = h1;
}

// -------------------- CSR build --------------------------------------------
__global__ void k_zero_cnt() {
    int i = blockIdx.x * blockDim.x + threadIdx.x;
    if (i < NN) g_cnt[i] = 0;
}

__global__ void k_count(const int* __restrict__ dst) {
    int e = blockIdx.x * blockDim.x + threadIdx.x;
    if (e < EE) atomicAdd(&g_cnt[dst[e]], 1);
}

__global__ void k_scan1() {
    __shared__ int sm[1024];
    int i = blockIdx.x * 1024 + threadIdx.x;
    int v = (i < NN) ? g_cnt[i] : 0;
    sm[threadIdx.x] = v;
    __syncthreads();
#pragma unroll
    for (int off = 1; off < 1024; off <<= 1) {
        int t = (threadIdx.x >= off) ? sm[threadIdx.x - off] : 0;
        __syncthreads();
        sm[threadIdx.x] += t;
        __syncthreads();
    }
    if (i < NN) g_row[i] = sm[threadIdx.x] - v;
    if (threadIdx.x == 1023) g_bsum[blockIdx.x] = sm[1023];
}

__global__ void k_scan2(int nb) {
    int t = threadIdx.x;
    int v = (t < nb) ? g_bsum[t] : 0;
    int lane = t & 31, w = t >> 5;
    int x = v;
#pragma unroll
    for (int off = 1; off < 32; off <<= 1) {
        int y = __shfl_up_sync(0xffffffffu, x, off);
        if (lane >= off) x += y;
    }
    __shared__ int ws[2];
    if (lane == 31) ws[w] = x;
    __syncthreads();
    if (w == 1) x += ws[0];
    if (t < nb) g_bsum[t] = x - v;   // exclusive
}

__global__ void k_scan3() {
    int i = blockIdx.x * blockDim.x + threadIdx.x;
    if (i < NN) {
        int v = g_row[i] + g_bsum[i >> 10];
        g_row[i] = v;
        g_pos[i] = v;
    }
}

__global__ void k_scatter(const int* __restrict__ src, const int* __restrict__ dst) {
    int e = blockIdx.x * blockDim.x + threadIdx.x;
    if (e < EE) {
        int d = dst[e];
        int p = atomicAdd(&g_pos[d], 1);
        g_csr_src[p] = src[e];
    }
}

// -------------------- tensor-core GEMM + el/er + fp16 emit ------------------
// Y = X[N,128] @ W[128,128] in fp16 HMMA, fp32 accum. MB=64 rows per block.
// 8 warps: wm = wid&3 (16 rows each), wn = wid>>2 (64 cols each).
__global__ void __launch_bounds__(256, 3) k_gemm_fused(const float* __restrict__ X,
                                                       const __half* __restrict__ Wh,
                                                       const float* __restrict__ al,
                                                       const float* __restrict__ ar) {
    __shared__ __half Xp[MB][KPAD];      // 17408 B ; epilogue reuses as Hs
    __shared__ __half Wp[FDIM][KPAD];    // 34816 B

    int t = threadIdx.x;
    int lane = t & 31, wid = t >> 5;
    int row0 = blockIdx.x * MB;

    // ---- fill smem ----
    // X: f32 -> f16 (64 rows x 128 cols = 2048 float4, 8 iters)
#pragma unroll
    for (int it = 0; it < 8; it++) {
        int i = t + it * 256;
        int r = i >> 5, c4 = (i & 31) * 4;
        int gr = row0 + r;
        float4 v = (gr < NN) ? *reinterpret_cast<const float4*>(&X[gr * FDIM + c4])
                             : make_float4(0.f, 0.f, 0.f, 0.f);
        *reinterpret_cast<__half2*>(&Xp[r][c4])     = __floats2half2_rn(v.x, v.y);
        *reinterpret_cast<__half2*>(&Xp[r][c4 + 2]) = __floats2half2_rn(v.z, v.w);
    }
    // W: already fp16, pure 16B copies (2048 uint4, 8 iters)
#pragma unroll
    for (int it = 0; it < 8; it++) {
        int i = t + it * 256;
        int r = i >> 4, c8 = (i & 15) * 8;
        *reinterpret_cast<uint4*>(&Wp[r][c8]) =
            reinterpret_cast<const uint4*>(Wh + r * FDIM)[c8 >> 3];
    }
    __syncthreads();

    int wm = wid & 3, wn = wid >> 2;
    float acc[8][4];
#pragma unroll
    for (int u = 0; u < 8; u++)
#pragma unroll
        for (int c = 0; c < 4; c++) acc[u][c] = 0.f;

    // ---- mainloop: 8 k16 steps ----
#pragma unroll
    for (int kk = 0; kk < 8; kk++) {
        unsigned A[4];
        {
            int r = wm * 16 + (lane & 15);
            int k = kk * 16 + ((lane >> 4) & 1) * 8;
            ldsm_x4(A, smaddr(&Xp[r][k]));
        }
        unsigned B[8][2];
#pragma unroll
        for (int ub = 0; ub < 4; ub++) {
            int kloc = kk * 16 + (lane & 7) + ((lane >> 3) & 1) * 8;
            int col = wn * 64 + (ub * 2 + ((lane >> 4) & 1)) * 8;
            unsigned r4[4];
            ldsm_x4_t(r4, smaddr(&Wp[kloc][col]));
            B[2 * ub][0] = r4[0]; B[2 * ub][1] = r4[1];
            B[2 * ub + 1][0] = r4[2]; B[2 * ub + 1][1] = r4[3];
        }
#pragma unroll
        for (int u = 0; u < 8; u++) mma16816(acc[u], A, B[u]);
    }
    __syncthreads();   // all reads of Xp/Wp done before Hs overwrite

    // ---- epilogue: head-interleaved fp16 emit into Hs (= Xp) ----
    __half (*Hs)[KPAD] = Xp;
#pragma unroll
    for (int u = 0; u < 8; u++) {
        int R = wm * 16 + (lane >> 2);
        int C = wn * 64 + u * 8 + (lane & 3) * 2;
        int p0 = ((C & 31) << 2) | (C >> 5);           // head-interleave
        Hs[R][p0]         = __float2half(acc[u][0]);
        Hs[R][p0 + 4]     = __float2half(acc[u][1]);
        Hs[R + 8][p0]     = __float2half(acc[u][2]);
        Hs[R + 8][p0 + 4] = __float2half(acc[u][3]);
    }
    __syncthreads();

    // ---- el/er from staged features: warp wid handles rows wid*8..+7 ----
    float alv[4], arv[4];
#pragma unroll
    for (int h = 0; h < 4; h++) {
        alv[h] = al[h * 32 + lane];
        arv[h] = ar[h * 32 + lane];
    }
#pragma unroll
    for (int i = 0; i < 8; i++) {
        int R = wid * 8 + i;
        int gr = row0 + R;
        uint2 uu = *reinterpret_cast<const uint2*>(&Hs[R][lane * 4]);
        float2 q0 = __half22float2(*reinterpret_cast<__half2*>(&uu.x));
        float2 q1 = __half22float2(*reinterpret_cast<__half2*>(&uu.y));
        float v0 = q0.x, v1 = q0.y, v2 = q1.x, v3 = q1.y;
        float l0 = v0 * alv[0], l1 = v1 * alv[1], l2 = v2 * alv[2], l3 = v3 * alv[3];
        float r0 = v0 * arv[0], r1 = v1 * arv[1], r2 = v2 * arv[2], r3 = v3 * arv[3];
#pragma unroll
        for (int off = 16; off; off >>= 1) {
            l0 += __shfl_xor_sync(0xffffffffu, l0, off);
            l1 += __shfl_xor_sync(0xffffffffu, l1, off);
            l2 += __shfl_xor_sync(0xffffffffu, l2, off);
            l3 += __shfl_xor_sync(0xffffffffu, l3, off);
            r0 += __shfl_xor_sync(0xffffffffu, r0, off);
            r1 += __shfl_xor_sync(0xffffffffu, r1, off);
            r2 += __shfl_xor_sync(0xffffffffu, r2, off);
            r3 += __shfl_xor_sync(0xffffffffu, r3, off);
        }
        if (lane == 0 && gr < NN) {
            g_el[gr * 4 + 0] = l0; g_el[gr * 4 + 1] = l1;
            g_el[gr * 4 + 2] = l2; g_el[gr * 4 + 3] = l3;
            g_er[gr * 4 + 0] = r0; g_er[gr * 4 + 1] = r1;
            g_er[gr * 4 + 2] = r2; g_er[gr * 4 + 3] = r3;
        }
    }

    // ---- coalesced fp16 feature write-out (16B chunks, 4 iters) ----
#pragma unroll
    for (int it = 0; it < 4; it++) {
        int i = t + it * 256;
        int r = i >> 4, c = i & 15;
        int gr = row0 + r;
        if (gr < NN)
            reinterpret_cast<uint4*>(g_feat_h + (size_t)gr * FDIM)[c] =
                *reinterpret_cast<const uint4*>(&Hs[r][c * 8]);
    }
}

// -------------------- single-pass warp-per-node softmax + SpMM --------------
#define AGG_WARPS 8

// MODE 1: layer1 -> elu, 128 feats (fp32) to g_h1. MODE 2: head-mean to out.
template <int MODE>
__global__ void __launch_bounds__(AGG_WARPS * 32) k_agg(const float* __restrict__ resid,
                                                        const float* __restrict__ bias,
                                                        float* __restrict__ out) {
    __shared__ __align__(16) float4 sm_w[AGG_WARPS][33];
    __shared__ int sm_s[AGG_WARPS][32];

    int wid  = threadIdx.x >> 5;
    int lane = threadIdx.x & 31;
    int node = blockIdx.x * AGG_WARPS + wid;
    if (node >= NN) return;

    int base = g_row[node];
    int deg  = g_cnt[node];
    float4 er4 = reinterpret_cast<const float4*>(g_er)[node];

    float sx = 0.f, sy = 0.f, sz = 0.f, sw = 0.f;
    float a0 = 0.f, a1 = 0.f, a2 = 0.f, a3 = 0.f;

    for (int c0 = 0; c0 < deg; c0 += 32) {
        int m = deg - c0; if (m > 32) m = 32;
        if (lane < m) {
            int s = g_csr_src[base + c0 + lane];
            float4 l4 = reinterpret_cast<const float4*>(g_el)[s];
            float4 w4;
            w4.x = __expf(lrelu(l4.x + er4.x));
            w4.y = __expf(lrelu(l4.y + er4.y));
            w4.z = __expf(lrelu(l4.z + er4.z));
            w4.w = __expf(lrelu(l4.w + er4.w));
            sx += w4.x; sy += w4.y; sz += w4.z; sw += w4.w;
            sm_s[wid][lane] = s;
            sm_w[wid][lane] = w4;
        }
        __syncwarp();
        int j = 0;
        for (; j + 3 < m; j += 4) {
            int   s0 = sm_s[wid][j];
            int   s1 = sm_s[wid][j + 1];
            int   s2 = sm_s[wid][j + 2];
            int   s3 = sm_s[wid][j + 3];
            float4 w0 = sm_w[wid][j];
            float4 w1 = sm_w[wid][j + 1];
            float4 w2 = sm_w[wid][j + 2];
            float4 w3 = sm_w[wid][j + 3];
            uint2 u0 = *reinterpret_cast<const uint2*>(g_feat_h + (size_t)s0 * FDIM + lane * 4);
            uint2 u1 = *reinterpret_cast<const uint2*>(g_feat_h + (size_t)s1 * FDIM + lane * 4);
            uint2 u2 = *reinterpret_cast<const uint2*>(g_feat_h + (size_t)s2 * FDIM + lane * 4);
            uint2 u3 = *reinterpret_cast<const uint2*>(g_feat_h + (size_t)s3 * FDIM + lane * 4);
            float2 f00 = __half22float2(*reinterpret_cast<__half2*>(&u0.x));
            float2 f01 = __half22float2(*reinterpret_cast<__half2*>(&u0.y));
            float2 f10 = __half22float2(*reinterpret_cast<__half2*>(&u1.x));
            float2 f11 = __half22float2(*reinterpret_cast<__half2*>(&u1.y));
            float2 f20 = __half22float2(*reinterpret_cast<__half2*>(&u2.x));
            float2 f21 = __half22float2(*reinterpret_cast<__half2*>(&u2.y));
            float2 f30 = __half22float2(*reinterpret_cast<__half2*>(&u3.x));
            float2 f31 = __half22float2(*reinterpret_cast<__half2*>(&u3.y));
            a0 += w0.x * f00.x + w1.x * f10.x + w2.x * f20.x + w3.x * f30.x;
            a1 += w0.y * f00.y + w1.y * f10.y + w2.y * f20.y + w3.y * f30.y;
            a2 += w0.z * f01.x + w1.z * f11.x + w2.z * f21.x + w3.z * f31.x;
            a3 += w0.w * f01.y + w1.w * f11.y + w2.w * f21.y + w3.w * f31.y;
        }
        for (; j < m; j++) {
            int   s0 = sm_s[wid][j];
            float4 w0 = sm_w[wid][j];
            uint2 u0 = *reinterpret_cast<const uint2*>(g_feat_h + (size_t)s0 * FDIM + lane * 4);
            float2 f00 = __half22float2(*reinterpret_cast<__half2*>(&u0.x));
            float2 f01 = __half22float2(*reinterpret_cast<__half2*>(&u0.y));
            a0 += w0.x * f00.x;
            a1 += w0.y * f00.y;
            a2 += w0.z * f01.x;
            a3 += w0.w * f01.y;
        }
        __syncwarp();
    }

#pragma unroll
    for (int off = 16; off; off >>= 1) {
        sx += __shfl_xor_sync(0xffffffffu, sx, off);
        sy += __shfl_xor_sync(0xffffffffu, sy, off);
        sz += __shfl_xor_sync(0xffffffffu, sz, off);
        sw += __shfl_xor_sync(0xffffffffu, sw, off);
    }
    float invx = 1.f / fmaxf(sx, 1e-9f);
    float invy = 1.f / fmaxf(sy, 1e-9f);
    float invz = 1.f / fmaxf(sz, 1e-9f);
    float invw = 1.f / fmaxf(sw, 1e-9f);

    float r0 = a0 * invx + resid[node * FDIM + 0  + lane] + bias[0  + lane];
    float r1 = a1 * invy + resid[node * FDIM + 32 + lane] + bias[32 + lane];
    float r2 = a2 * invz + resid[node * FDIM + 64 + lane] + bias[64 + lane];
    float r3 = a3 * invw + resid[node * FDIM + 96 + lane] + bias[96 + lane];

    if (MODE == 1) {
        out[node * FDIM + 0  + lane] = elu1(r0);
        out[node * FDIM + 32 + lane] = elu1(r1);
        out[node * FDIM + 64 + lane] = elu1(r2);
        out[node * FDIM + 96 + lane] = elu1(r3);
    } else {
        out[node * 32 + lane] = 0.25f * (r0 + r1 + r2 + r3);
    }
}

// -------------------- launch ------------------------------------------------
extern "C" void kernel_launch(void* const* d_in, const int* in_sizes, int n_in,
                              void* d_out, int out_size) {
    const float* x   = (const float*)d_in[0];
    const float* W1  = (const float*)d_in[1];
    const float* al1 = (const float*)d_in[2];
    const float* ar1 = (const float*)d_in[3];
    const float* b1  = (const float*)d_in[4];
    const float* W2  = (const float*)d_in[5];
    const float* al2 = (const float*)d_in[6];
    const float* ar2 = (const float*)d_in[7];
    const float* b2  = (const float*)d_in[8];
    const int*   src = (const int*)d_in[9];
    const int*   dst = (const int*)d_in[10];
    float* out = (float*)d_out;

    float* h1 = nullptr;
    __half* wh = nullptr;
    cudaGetSymbolAddress((void**)&h1, g_h1);
    cudaGetSymbolAddress((void**)&wh, g_Wh);

    const int TB = 256;
    int nblkN = (NN + TB - 1) / TB;
    int nblkE = (EE + TB - 1) / TB;
    int nScan = (NN + 1023) / 1024;                 // 49
    int nAgg  = (NN + AGG_WARPS - 1) / AGG_WARPS;   // 6250
    int nGemm = (NN + MB - 1) / MB;                 // 782
    int nWc   = (FDIM * FDIM / 4 + TB - 1) / TB;    // 16

    // layer-1 GEMM kept at launch slot 4 (profiled slot).
    k_zero_cnt<<<nblkN, TB>>>();                          // 1
    k_wconv<<<nWc, TB>>>(W1, 0);                          // 2
    k_wconv<<<nWc, TB>>>(W2, 1);                          // 3
    k_gemm_fused<<<nGemm, 256>>>(x, wh, al1, ar1);        // 4  <- profiled
    k_count<<<nblkE, TB>>>(dst);                          // 5
    k_scan1<<<nScan, 1024>>>();                           // 6
    k_scan2<<<1, 64>>>(nScan);                            // 7
    k_scan3<<<nblkN, TB>>>();                             // 8
    k_scatter<<<nblkE, TB>>>(src, dst);                   // 9
    k_agg<1><<<nAgg, AGG_WARPS * 32>>>(x, b1, h1);        // 10
    k_gemm_fused<<<nGemm, 256>>>(h1, wh + FDIM * FDIM, al2, ar2); // 11
    k_agg<2><<<nAgg, AGG_WARPS * 32>>>(h1, b2, out);      // 12
}

// round 12
// speedup vs baseline: 1.4585x; 1.0082x over previous
#include <cuda_runtime.h>
#include <cuda_fp16.h>
#include <cuda_bf16.h>

// ---------------------------------------------------------------------------
// GAT (2-layer, H=4, D=32, IN=128) on GB300, round 12.
//  - HMMA GEMM: 2 M-tiles per block (grid=391, single wave), W staged in smem
//    ONCE per block; fp16 W pre-converted in gmem (one merged k_wconv).
//  - scan2 folded into scan3 (redundant 49-elem prefix per block).
//  - el/er + head-interleaved fp16 feature emit fused in epilogue (unchanged).
//  - CSR build + single-pass warp-per-node agg (unchanged, best known).
// ---------------------------------------------------------------------------

#define NN 50000
#define EE 800000
#define FDIM 128
#define NEG_SLOPE 0.2f
#define MB 64                  // GEMM rows per tile
#define KPAD 136               // padded smem row (halves); 272B stride
#define NGEMM ((NN + MB - 1) / MB)     // 782
#define GEMM_GRID 391                  // 2 tiles per block, single wave
#define NSCAN 49                       // ceil(50000/1024)

typedef unsigned long long ull;

// -------------------- scratch (static device globals) ----------------------
__device__ __half g_feat_h[NN * FDIM];   // 12.8 MB fp16 features, head-interleaved
__device__ float  g_h1[NN * FDIM];       // 25.6 MB layer-1 output
__device__ __half g_Wh[2][FDIM * FDIM];  // 64 KB   fp16 weights (pre-converted)
__device__ int    g_csr_src[EE];         //  3.2 MB
__device__ int    g_cnt[NN];
__device__ int    g_row[NN];
__device__ int    g_pos[NN];
__device__ float  g_el[NN * 4];
__device__ float  g_er[NN * 4];
__device__ int    g_bsum[64];

// -------------------- math helpers ------------------------------------------
__device__ __forceinline__ float lrelu(float x) { return x > 0.f ? x : NEG_SLOPE * x; }
__device__ __forceinline__ float elu1(float x)  { return x > 0.f ? x : (__expf(x) - 1.f); }

__device__ __forceinline__ unsigned smaddr(const void* p) {
    return (unsigned)__cvta_generic_to_shared(p);
}
__device__ __forceinline__ void ldsm_x4(unsigned* r, unsigned addr) {
    asm volatile("ldmatrix.sync.aligned.m8n8.x4.shared.b16 {%0,%1,%2,%3}, [%4];"
                 : "=r"(r[0]), "=r"(r[1]), "=r"(r[2]), "=r"(r[3]) : "r"(addr));
}
__device__ __forceinline__ void ldsm_x4_t(unsigned* r, unsigned addr) {
    asm volatile("ldmatrix.sync.aligned.m8n8.x4.trans.shared.b16 {%0,%1,%2,%3}, [%4];"
                 : "=r"(r[0]), "=r"(r[1]), "=r"(r[2]), "=r"(r[3]) : "r"(addr));
}
__device__ __forceinline__ void mma16816(float* d, const unsigned* a, const unsigned* b) {
    asm volatile("mma.sync.aligned.m16n8k16.row.col.f32.f16.f16.f32 "
                 "{%0,%1,%2,%3}, {%4,%5,%6,%7}, {%8,%9}, {%0,%1,%2,%3};"
                 : "+f"(d[0]), "+f"(d[1]), "+f"(d[2]), "+f"(d[3])
                 : "r"(a[0]), "r"(a[1]), "r"(a[2]), "r"(a[3]), "r"(b[0]), "r"(b[1]));
}

// -------------------- weight pre-convert (both layers, one launch) ----------
__global__ void k_wconv(const float* __restrict__ W1, const float* __restrict__ W2) {
    int i = blockIdx.x * blockDim.x + threadIdx.x;      // over 2*4096 float4
    if (i >= 2 * FDIM * FDIM / 4) return;
    int slot = i >= FDIM * FDIM / 4;
    int j = i - slot * (FDIM * FDIM / 4);
    const float* W = slot ? W2 : W1;
    float4 v = reinterpret_cast<const float4*>(W)[j];
    __half2 h0 = __floats2half2_rn(v.x, v.y);
    __half2 h1 = __floats2half2_rn(v.z, v.w);
    reinterpret_cast<__half2*>(g_Wh[slot])[j * 2]     = h0;
    reinterpret_cast<__half2*>(g_Wh[slot])[j * 2 + 1] = h1;
}

// -------------------- CSR build --------------------------------------------
__global__ void k_zero_cnt() {
    int i = blockIdx.x * blockDim.x + threadIdx.x;
    if (i < NN) g_cnt[i] = 0;
}

__global__ void k_count(const int* __restrict__ dst) {
    int e = blockIdx.x * blockDim.x + threadIdx.x;
    if (e < EE) atomicAdd(&g_cnt[dst[e]], 1);
}

__global__ void k_scan1() {
    __shared__ int sm[1024];
    int i = blockIdx.x * 1024 + threadIdx.x;
    int v = (i < NN) ? g_cnt[i] : 0;
    sm[threadIdx.x] = v;
    __syncthreads();
#pragma unroll
    for (int off = 1; off < 1024; off <<= 1) {
        int t = (threadIdx.x >= off) ? sm[threadIdx.x - off] : 0;
        __syncthreads();
        sm[threadIdx.x] += t;
        __syncthreads();
    }
    if (i < NN) g_row[i] = sm[threadIdx.x] - v;
    if (threadIdx.x == 1023) g_bsum[blockIdx.x] = sm[1023];
}

// scan of the 49 block sums folded in (computed redundantly per block)
__global__ void k_scan3() {
    __shared__ int pre[64];
    int t = threadIdx.x;
    if (t < 64) {
        int v = (t < NSCAN) ? g_bsum[t] : 0;
        int lane = t & 31, w = t >> 5;
        int x = v;
#pragma unroll
        for (int off = 1; off < 32; off <<= 1) {
            int y = __shfl_up_sync(0xffffffffu, x, off);
            if (lane >= off) x += y;
        }
        pre[t] = x - v;          // exclusive within warp
        if (lane == 31) pre[w] = x;   // temporarily stash warp totals? (avoid: see below)
    }
    __syncthreads();
    // fix cross-warp: recompute cleanly with a single thread (cheap, 64 ints)
    __shared__ int pre2[64];
    if (t == 0) {
        int s = 0;
        for (int i = 0; i < NSCAN; i++) { int v = g_bsum[i]; pre2[i] = s; s += v; }
    }
    __syncthreads();
    int i = blockIdx.x * blockDim.x + t;
    if (i < NN) {
        int v = g_row[i] + pre2[i >> 10];
        g_row[i] = v;
        g_pos[i] = v;
    }
}

__global__ void k_scatter(const int* __restrict__ src, const int* __restrict__ dst) {
    int e = blockIdx.x * blockDim.x + threadIdx.x;
    if (e < EE) {
        int d = dst[e];
        int p = atomicAdd(&g_pos[d], 1);
        g_csr_src[p] = src[e];
    }
}

// -------------------- tensor-core GEMM + el/er + fp16 emit ------------------
// Y = X[N,128] @ W[128,128] fp16 HMMA, fp32 accum. 2 tiles of MB=64 rows per
// block; W staged once. 8 warps: wm=wid&3 (16 rows), wn=wid>>2 (64 cols).
__global__ void __launch_bounds__(256, 3) k_gemm_fused(const float* __restrict__ X,
                                                       const __half* __restrict__ Wh,
                                                       const float* __restrict__ al,
                                                       const float* __restrict__ ar) {
    __shared__ __half Xp[MB][KPAD];      // 17408 B ; epilogue reuses as Hs
    __shared__ __half Wp[FDIM][KPAD];    // 34816 B (persistent across tiles)

    int t = threadIdx.x;
    int lane = t & 31, wid = t >> 5;
    int wm = wid & 3, wn = wid >> 2;

    // ---- W fill ONCE (pure 16B copies, 8 iters) ----
#pragma unroll
    for (int it = 0; it < 8; it++) {
        int i = t + it * 256;
        int r = i >> 4, c8 = (i & 15) * 8;
        *reinterpret_cast<uint4*>(&Wp[r][c8]) =
            reinterpret_cast<const uint4*>(Wh + r * FDIM)[c8 >> 3];
    }

    float alv[4], arv[4];
#pragma unroll
    for (int h = 0; h < 4; h++) {
        alv[h] = al[h * 32 + lane];
        arv[h] = ar[h * 32 + lane];
    }

    for (int tile = blockIdx.x; tile < NGEMM; tile += GEMM_GRID) {
        int row0 = tile * MB;

        // ---- X fill: f32 -> f16 (8 iters). Xp may hold last tile's Hs;
        // all its readers finished before the loop-end __syncthreads().
#pragma unroll
        for (int it = 0; it < 8; it++) {
            int i = t + it * 256;
            int r = i >> 5, c4 = (i & 31) * 4;
            int gr = row0 + r;
            float4 v = (gr < NN) ? *reinterpret_cast<const float4*>(&X[gr * FDIM + c4])
                                 : make_float4(0.f, 0.f, 0.f, 0.f);
            *reinterpret_cast<__half2*>(&Xp[r][c4])     = __floats2half2_rn(v.x, v.y);
            *reinterpret_cast<__half2*>(&Xp[r][c4 + 2]) = __floats2half2_rn(v.z, v.w);
        }
        __syncthreads();

        float acc[8][4];
#pragma unroll
        for (int u = 0; u < 8; u++)
#pragma unroll
            for (int c = 0; c < 4; c++) acc[u][c] = 0.f;

        // ---- mainloop: 8 k16 steps ----
#pragma unroll
        for (int kk = 0; kk < 8; kk++) {
            unsigned A[4];
            {
                int r = wm * 16 + (lane & 15);
                int k = kk * 16 + ((lane >> 4) & 1) * 8;
                ldsm_x4(A, smaddr(&Xp[r][k]));
            }
            unsigned B[8][2];
#pragma unroll
            for (int ub = 0; ub < 4; ub++) {
                int kloc = kk * 16 + (lane & 7) + ((lane >> 3) & 1) * 8;
                int col = wn * 64 + (ub * 2 + ((lane >> 4) & 1)) * 8;
                unsigned r4[4];
                ldsm_x4_t(r4, smaddr(&Wp[kloc][col]));
                B[2 * ub][0] = r4[0]; B[2 * ub][1] = r4[1];
                B[2 * ub + 1][0] = r4[2]; B[2 * ub + 1][1] = r4[3];
            }
#pragma unroll
            for (int u = 0; u < 8; u++) mma16816(acc[u], A, B[u]);
        }
        __syncthreads();   // all Xp reads done before Hs overwrite

        // ---- epilogue: head-interleaved fp16 emit into Hs (= Xp) ----
        __half (*Hs)[KPAD] = Xp;
#pragma unroll
        for (int u = 0; u < 8; u++) {
            int R = wm * 16 + (lane >> 2);
            int C = wn * 64 + u * 8 + (lane & 3) * 2;
            int p0 = ((C & 31) << 2) | (C >> 5);           // head-interleave
            Hs[R][p0]         = __float2half(acc[u][0]);
            Hs[R][p0 + 4]     = __float2half(acc[u][1]);
            Hs[R + 8][p0]     = __float2half(acc[u][2]);
            Hs[R + 8][p0 + 4] = __float2half(acc[u][3]);
        }
        __syncthreads();

        // ---- el/er: warp wid handles rows wid*8..+7 ----
#pragma unroll
        for (int i = 0; i < 8; i++) {
            int R = wid * 8 + i;
            int gr = row0 + R;
            uint2 uu = *reinterpret_cast<const uint2*>(&Hs[R][lane * 4]);
            float2 q0 = __half22float2(*reinterpret_cast<__half2*>(&uu.x));
            float2 q1 = __half22float2(*reinterpret_cast<__half2*>(&uu.y));
            float v0 = q0.x, v1 = q0.y, v2 = q1.x, v3 = q1.y;
            float l0 = v0 * alv[0], l1 = v1 * alv[1], l2 = v2 * alv[2], l3 = v3 * alv[3];
            float r0 = v0 * arv[0], r1 = v1 * arv[1], r2 = v2 * arv[2], r3 = v3 * arv[3];
#pragma unroll
            for (int off = 16; off; off >>= 1) {
                l0 += __shfl_xor_sync(0xffffffffu, l0, off);
                l1 += __shfl_xor_sync(0xffffffffu, l1, off);
                l2 += __shfl_xor_sync(0xffffffffu, l2, off);
                l3 += __shfl_xor_sync(0xffffffffu, l3, off);
                r0 += __shfl_xor_sync(0xffffffffu, r0, off);
                r1 += __shfl_xor_sync(0xffffffffu, r1, off);
                r2 += __shfl_xor_sync(0xffffffffu, r2, off);
                r3 += __shfl_xor_sync(0xffffffffu, r3, off);
            }
            if (lane == 0 && gr < NN) {
                g_el[gr * 4 + 0] = l0; g_el[gr * 4 + 1] = l1;
                g_el[gr * 4 + 2] = l2; g_el[gr * 4 + 3] = l3;
                g_er[gr * 4 + 0] = r0; g_er[gr * 4 + 1] = r1;
                g_er[gr * 4 + 2] = r2; g_er[gr * 4 + 3] = r3;
            }
        }

        // ---- coalesced fp16 feature write-out (16B chunks, 4 iters) ----
#pragma unroll
        for (int it = 0; it < 4; it++) {
            int i = t + it * 256;
            int r = i >> 4, c = i & 15;
            int gr = row0 + r;
            if (gr < NN)
                reinterpret_cast<uint4*>(g_feat_h + (size_t)gr * FDIM)[c] =
                    *reinterpret_cast<const uint4*>(&Hs[r][c * 8]);
        }
        __syncthreads();   // Hs reads done before next tile's Xp fill
    }
}

// -------------------- single-pass warp-per-node softmax + SpMM --------------
#define AGG_WARPS 8

// MODE 1: layer1 -> elu, 128 feats (fp32) to g_h1. MODE 2: head-mean to out.
template <int MODE>
__global__ void __launch_bounds__(AGG_WARPS * 32) k_agg(const float* __restrict__ resid,
                                                        const float* __restrict__ bias,
                                                        float* __restrict__ out) {
    __shared__ __align__(16) float4 sm_w[AGG_WARPS][33];
    __shared__ int sm_s[AGG_WARPS][32];

    int wid  = threadIdx.x >> 5;
    int lane = threadIdx.x & 31;
    int node = blockIdx.x * AGG_WARPS + wid;
    if (node >= NN) return;

    int base = g_row[node];
    int deg  = g_cnt[node];
    float4 er4 = reinterpret_cast<const float4*>(g_er)[node];

    float sx = 0.f, sy = 0.f, sz = 0.f, sw = 0.f;
    float a0 = 0.f, a1 = 0.f, a2 = 0.f, a3 = 0.f;

    for (int c0 = 0; c0 < deg; c0 += 32) {
        int m = deg - c0; if (m > 32) m = 32;
        if (lane < m) {
            int s = g_csr_src[base + c0 + lane];
            float4 l4 = reinterpret_cast<const float4*>(g_el)[s];
            float4 w4;
            w4.x = __expf(lrelu(l4.x + er4.x));
            w4.y = __expf(lrelu(l4.y + er4.y));
            w4.z = __expf(lrelu(l4.z + er4.z));
            w4.w = __expf(lrelu(l4.w + er4.w));
            sx += w4.x; sy += w4.y; sz += w4.z; sw += w4.w;
            sm_s[wid][lane] = s;
            sm_w[wid][lane] = w4;
        }
        __syncwarp();
        int j = 0;
        for (; j + 3 < m; j += 4) {
            int   s0 = sm_s[wid][j];
            int   s1 = sm_s[wid][j + 1];
            int   s2 = sm_s[wid][j + 2];
            int   s3 = sm_s[wid][j + 3];
            float4 w0 = sm_w[wid][j];
            float4 w1 = sm_w[wid][j + 1];
            float4 w2 = sm_w[wid][j + 2];
            float4 w3 = sm_w[wid][j + 3];
            uint2 u0 = *reinterpret_cast<const uint2*>(g_feat_h + (size_t)s0 * FDIM + lane * 4);
            uint2 u1 = *reinterpret_cast<const uint2*>(g_feat_h + (size_t)s1 * FDIM + lane * 4);
            uint2 u2 = *reinterpret_cast<const uint2*>(g_feat_h + (size_t)s2 * FDIM + lane * 4);
            uint2 u3 = *reinterpret_cast<const uint2*>(g_feat_h + (size_t)s3 * FDIM + lane * 4);
            float2 f00 = __half22float2(*reinterpret_cast<__half2*>(&u0.x));
            float2 f01 = __half22float2(*reinterpret_cast<__half2*>(&u0.y));
            float2 f10 = __half22float2(*reinterpret_cast<__half2*>(&u1.x));
            float2 f11 = __half22float2(*reinterpret_cast<__half2*>(&u1.y));
            float2 f20 = __half22float2(*reinterpret_cast<__half2*>(&u2.x));
            float2 f21 = __half22float2(*reinterpret_cast<__half2*>(&u2.y));
            float2 f30 = __half22float2(*reinterpret_cast<__half2*>(&u3.x));
            float2 f31 = __half22float2(*reinterpret_cast<__half2*>(&u3.y));
            a0 += w0.x * f00.x + w1.x * f10.x + w2.x * f20.x + w3.x * f30.x;
            a1 += w0.y * f00.y + w1.y * f10.y + w2.y * f20.y + w3.y * f30.y;
            a2 += w0.z * f01.x + w1.z * f11.x + w2.z * f21.x + w3.z * f31.x;
            a3 += w0.w * f01.y + w1.w * f11.y + w2.w * f21.y + w3.w * f31.y;
        }
        for (; j < m; j++) {
            int   s0 = sm_s[wid][j];
            float4 w0 = sm_w[wid][j];
            uint2 u0 = *reinterpret_cast<const uint2*>(g_feat_h + (size_t)s0 * FDIM + lane * 4);
            float2 f00 = __half22float2(*reinterpret_cast<__half2*>(&u0.x));
            float2 f01 = __half22float2(*reinterpret_cast<__half2*>(&u0.y));
            a0 += w0.x * f00.x;
            a1 += w0.y * f00.y;
            a2 += w0.z * f01.x;
            a3 += w0.w * f01.y;
        }
        __syncwarp();
    }

#pragma unroll
    for (int off = 16; off; off >>= 1) {
        sx += __shfl_xor_sync(0xffffffffu, sx, off);
        sy += __shfl_xor_sync(0xffffffffu, sy, off);
        sz += __shfl_xor_sync(0xffffffffu, sz, off);
        sw += __shfl_xor_sync(0xffffffffu, sw, off);
    }
    float invx = 1.f / fmaxf(sx, 1e-9f);
    float invy = 1.f / fmaxf(sy, 1e-9f);
    float invz = 1.f / fmaxf(sz, 1e-9f);
    float invw = 1.f / fmaxf(sw, 1e-9f);

    float r0 = a0 * invx + resid[node * FDIM + 0  + lane] + bias[0  + lane];
    float r1 = a1 * invy + resid[node * FDIM + 32 + lane] + bias[32 + lane];
    float r2 = a2 * invz + resid[node * FDIM + 64 + lane] + bias[64 + lane];
    float r3 = a3 * invw + resid[node * FDIM + 96 + lane] + bias[96 + lane];

    if (MODE == 1) {
        out[node * FDIM + 0  + lane] = elu1(r0);
        out[node * FDIM + 32 + lane] = elu1(r1);
        out[node * FDIM + 64 + lane] = elu1(r2);
        out[node * FDIM + 96 + lane] = elu1(r3);
    } else {
        out[node * 32 + lane] = 0.25f * (r0 + r1 + r2 + r3);
    }
}

// -------------------- launch ------------------------------------------------
extern "C" void kernel_launch(void* const* d_in, const int* in_sizes, int n_in,
                              void* d_out, int out_size) {
    const float* x   = (const float*)d_in[0];
    const float* W1  = (const float*)d_in[1];
    const float* al1 = (const float*)d_in[2];
    const float* ar1 = (const float*)d_in[3];
    const float* b1  = (const float*)d_in[4];
    const float* W2  = (const float*)d_in[5];
    const float* al2 = (const float*)d_in[6];
    const float* ar2 = (const float*)d_in[7];
    const float* b2  = (const float*)d_in[8];
    const int*   src = (const int*)d_in[9];
    const int*   dst = (const int*)d_in[10];
    float* out = (float*)d_out;

    float* h1 = nullptr;
    __half* wh = nullptr;
    cudaGetSymbolAddress((void**)&h1, g_h1);
    cudaGetSymbolAddress((void**)&wh, g_Wh);

    const int TB = 256;
    int nblkN = (NN + TB - 1) / TB;                 // 196
    int nblkE = (EE + TB - 1) / TB;                 // 3125
    int nAgg  = (NN + AGG_WARPS - 1) / AGG_WARPS;   // 6250
    int nWc   = (2 * FDIM * FDIM / 4 + TB - 1) / TB; // 32

    // layer-1 GEMM kept at launch slot 4 (profiled slot).
    k_wconv<<<nWc, TB>>>(W1, W2);                         // 1
    k_zero_cnt<<<nblkN, TB>>>();                          // 2
    k_count<<<nblkE, TB>>>(dst);                          // 3
    k_gemm_fused<<<GEMM_GRID, 256>>>(x, wh, al1, ar1);    // 4  <- profiled
    k_scan1<<<NSCAN, 1024>>>();                           // 5
    k_scan3<<<nblkN, TB>>>();                             // 6
    k_scatter<<<nblkE, TB>>>(src, dst);                   // 7
    k_agg<1><<<nAgg, AGG_WARPS * 32>>>(x, b1, h1);        // 8
    k_gemm_fused<<<GEMM_GRID, 256>>>(h1, wh + FDIM * FDIM, al2, ar2); // 9
    k_agg<2><<<nAgg, AGG_WARPS * 32>>>(h1, b2, out);      // 10
}